// round 9
// baseline (speedup 1.0000x reference)
#include <cuda_runtime.h>
#include <cuda_fp16.h>
#include <cstddef>
#include <cstdint>

#define BATCH   64
#define NCAPS   32
#define NROUTES 2048
#define INDIM   16
#define OUTDIM  32
#define NITERS  3
#define THREADS 512
#define NWARPS  16

// Prior rows stored as half2[16] with stride 17 (half2 units) -> conflict-free
#define SPH 17

// ---- SMEM layout (float units) ----
// sp0 : half2[1024][SPH]  (batch 0)            17408 floats
// sp1 : half2[1024][SPH]  (batch 1)            17408 floats
// xs  : float4[2][512][5] (x stage, quarter)   20480 floats (stride 5 -> LDS conflict-free)
// scratch: Vsh[32] sred[32] wred[16] wvec[16*32] scal[4]
#define OFF_SP0   0
#define OFF_SP1   17408
#define OFF_XS    34816
#define OFF_SCR   55296
#define N_SCRATCH (32 + 32 + 16 + NWARPS * 32 + 4)
#define SMEM_BYTES ((OFF_SCR + N_SCRATCH) * 4)          // 223,568 B

#define XS_F4_PER_B (512 * 5)   // float4s per batch in the stage buffer

// Quad-route warp scheme: lane l -> route (r4 + l/8), cols 4*(l%8)..+3.
// W streams from global (16 LDG.128/quad); x comes from SMEM stage (LDS.128).
__device__ __forceinline__ void quad2s(const float4* __restrict__ xs4,
                                       const float* __restrict__ W,
                                       int c, int rglob4, int rloc4,
                                       int rsub, int c4,
                                       float aX[4], float aY[4])
{
    const int rg = rglob4 + rsub;
    const int rl = rloc4 + rsub;
    const float4* wr  = reinterpret_cast<const float4*>(
        W + ((size_t)c * NROUTES + rg) * (INDIM * OUTDIM)) + c4;   // stride per i: 8 float4
    const float4* xa4 = xs4 + (size_t)rl * 5;                 // batch 0
    const float4* xb4 = xs4 + XS_F4_PER_B + (size_t)rl * 5;   // batch 1

    aX[0] = aX[1] = aX[2] = aX[3] = 0.f;
    aY[0] = aY[1] = aY[2] = aY[3] = 0.f;

#pragma unroll
    for (int g = 0; g < 4; g++) {
        float4 w0 = __ldg(wr + (g * 4 + 0) * 8);
        float4 w1 = __ldg(wr + (g * 4 + 1) * 8);
        float4 w2 = __ldg(wr + (g * 4 + 2) * 8);
        float4 w3 = __ldg(wr + (g * 4 + 3) * 8);
        float4 xa = xa4[g];
        float4 xb = xb4[g];

        aX[0] = fmaf(xa.x, w0.x, aX[0]); aX[1] = fmaf(xa.x, w0.y, aX[1]);
        aX[2] = fmaf(xa.x, w0.z, aX[2]); aX[3] = fmaf(xa.x, w0.w, aX[3]);
        aX[0] = fmaf(xa.y, w1.x, aX[0]); aX[1] = fmaf(xa.y, w1.y, aX[1]);
        aX[2] = fmaf(xa.y, w1.z, aX[2]); aX[3] = fmaf(xa.y, w1.w, aX[3]);
        aX[0] = fmaf(xa.z, w2.x, aX[0]); aX[1] = fmaf(xa.z, w2.y, aX[1]);
        aX[2] = fmaf(xa.z, w2.z, aX[2]); aX[3] = fmaf(xa.z, w2.w, aX[3]);
        aX[0] = fmaf(xa.w, w3.x, aX[0]); aX[1] = fmaf(xa.w, w3.y, aX[1]);
        aX[2] = fmaf(xa.w, w3.z, aX[2]); aX[3] = fmaf(xa.w, w3.w, aX[3]);

        aY[0] = fmaf(xb.x, w0.x, aY[0]); aY[1] = fmaf(xb.x, w0.y, aY[1]);
        aY[2] = fmaf(xb.x, w0.z, aY[2]); aY[3] = fmaf(xb.x, w0.w, aY[3]);
        aY[0] = fmaf(xb.y, w1.x, aY[0]); aY[1] = fmaf(xb.y, w1.y, aY[1]);
        aY[2] = fmaf(xb.y, w1.z, aY[2]); aY[3] = fmaf(xb.y, w1.w, aY[3]);
        aY[0] = fmaf(xb.z, w2.x, aY[0]); aY[1] = fmaf(xb.z, w2.y, aY[1]);
        aY[2] = fmaf(xb.z, w2.z, aY[2]); aY[3] = fmaf(xb.z, w2.w, aY[3]);
        aY[0] = fmaf(xb.w, w3.x, aY[0]); aY[1] = fmaf(xb.w, w3.y, aY[1]);
        aY[2] = fmaf(xb.w, w3.z, aY[2]); aY[3] = fmaf(xb.w, w3.w, aY[3]);
    }
}

__global__ void __launch_bounds__(THREADS, 1)
caps_route_kernel(const float* __restrict__ x,
                  const float* __restrict__ W,
                  float* __restrict__ out)
{
    extern __shared__ float smbase[];
    __half2* sp0 = reinterpret_cast<__half2*>(smbase + OFF_SP0);
    __half2* sp1 = reinterpret_cast<__half2*>(smbase + OFF_SP1);
    float4*  xs4 = reinterpret_cast<float4*>(smbase + OFF_XS);
    float* scr  = smbase + OFF_SCR;
    float* Vsh  = scr;                      // 32
    float* sred = scr + 32;                 // 32
    float* wred = scr + 64;                 // 16
    float* wvec = scr + 80;                 // 16*32
    float* scal = scr + 80 + NWARPS * 32;   // 4

    const int t    = threadIdx.x;
    const int lane = t & 31;
    const int wid  = t >> 5;
    const int rsub = lane >> 3;
    const int c4   = lane & 7;
    const int bp   = blockIdx.x & (NCAPS - 1);   // 0..31
    const int c    = blockIdx.x >> 5;
    const int b0   = 2 * bp, b1 = 2 * bp + 1;

    __half2 A0[16], B0[16], A1[16], B1[16];

    // ---------------- Phase 1: four 512-route quarters ----------------
    for (int quarter = 0; quarter < 4; quarter++) {
        const int rq = quarter * 512;            // global route base

        // Stage x (both batches) for this quarter: 4096 float4s
        for (int idx = t; idx < 2 * 512 * 4; idx += THREADS) {
            const int bsel = idx >> 11;
            const int rem  = idx & 2047;
            const int r    = rem >> 2;
            const int q    = rem & 3;
            float4 v = __ldg(reinterpret_cast<const float4*>(
                x + ((size_t)(b0 + bsel) * NROUTES + rq + r) * INDIM) + q);
            xs4[(size_t)bsel * XS_F4_PER_B + (size_t)r * 5 + q] = v;
        }
        __syncthreads();

        // Compute: warp wid owns quarter-local routes [wid*32, wid*32+32)
        const int base = wid * 32;
        const int rowbase = rq & 1023;
#pragma unroll 2
        for (int j = 0; j < 32; j += 4) {
            float aX[4], aY[4];
            quad2s(xs4, W, c, rq + base + j, base + j, rsub, c4, aX, aY);
            const int row = rowbase + base + j + rsub;
            __half2* r0 = sp0 + (size_t)row * SPH + c4 * 2;
            __half2* r1 = sp1 + (size_t)row * SPH + c4 * 2;
            r0[0] = __floats2half2_rn(aX[0], aX[1]);
            r0[1] = __floats2half2_rn(aX[2], aX[3]);
            r1[0] = __floats2half2_rn(aY[0], aY[1]);
            r1[1] = __floats2half2_rn(aY[2], aY[3]);
        }
        __syncthreads();

        if (quarter == 1) {
            // routes 0..1023 complete: pull register rows (t, t+512 per batch)
            const __half2* pA0 = sp0 + (size_t)t * SPH;
            const __half2* pB0 = sp0 + (size_t)(512 + t) * SPH;
            const __half2* pA1 = sp1 + (size_t)t * SPH;
            const __half2* pB1 = sp1 + (size_t)(512 + t) * SPH;
#pragma unroll
            for (int j = 0; j < 16; j++) {
                A0[j] = pA0[j]; B0[j] = pB0[j];
                A1[j] = pA1[j]; B1[j] = pB1[j];
            }
            __syncthreads();   // pull done before quarter 2 overwrites rows
        }
    }

    // ---------------- Phase 2: routing, batch-sequential ----------------
    for (int bb = 0; bb < 2; bb++) {
        const __half2* A   = bb ? A1 : A0;
        const __half2* B   = bb ? B1 : B0;
        const __half2* spC = (bb ? sp1 : sp0) + (size_t)t * SPH;          // route 1024+t
        const __half2* spD = (bb ? sp1 : sp0) + (size_t)(512 + t) * SPH;  // route 1536+t
        const int bout = bb ? b1 : b0;

        if (t < 32) Vsh[t] = 0.f;
        __syncthreads();

        for (int it = 0; it < NITERS; it++) {
            float p0, p1, p2, p3;
            if (it == 0) {
                p0 = p1 = p2 = p3 = 1.0f / (float)NROUTES;
            } else {
                float l0 = 0.f, l1 = 0.f, l2 = 0.f, l3 = 0.f;
#pragma unroll
                for (int j = 0; j < 16; j++) {
                    float v0 = Vsh[2 * j], v1 = Vsh[2 * j + 1];
                    float2 a = __half22float2(A[j]);
                    float2 b2 = __half22float2(B[j]);
                    float2 cc = __half22float2(spC[j]);
                    float2 dd = __half22float2(spD[j]);
                    l0 += a.x * v0 + a.y * v1;
                    l1 += b2.x * v0 + b2.y * v1;
                    l2 += cc.x * v0 + cc.y * v1;
                    l3 += dd.x * v0 + dd.y * v1;
                }
                float m = fmaxf(fmaxf(l0, l1), fmaxf(l2, l3));
#pragma unroll
                for (int s = 16; s; s >>= 1) m = fmaxf(m, __shfl_xor_sync(0xffffffffu, m, s));
                if (lane == 0) wred[wid] = m;
                __syncthreads();
                if (wid == 0) {
                    float mm = (lane < NWARPS) ? wred[lane] : -3.402823e38f;
#pragma unroll
                    for (int s = 16; s; s >>= 1) mm = fmaxf(mm, __shfl_xor_sync(0xffffffffu, mm, s));
                    if (lane == 0) scal[0] = mm;
                }
                __syncthreads();
                const float bmax = scal[0];

                float e0 = __expf(l0 - bmax);
                float e1 = __expf(l1 - bmax);
                float e2 = __expf(l2 - bmax);
                float e3 = __expf(l3 - bmax);
                float zs = e0 + e1 + e2 + e3;
#pragma unroll
                for (int s = 16; s; s >>= 1) zs += __shfl_xor_sync(0xffffffffu, zs, s);
                if (lane == 0) wred[wid] = zs;
                __syncthreads();
                if (wid == 0) {
                    float zz = (lane < NWARPS) ? wred[lane] : 0.f;
#pragma unroll
                    for (int s = 16; s; s >>= 1) zz += __shfl_xor_sync(0xffffffffu, zz, s);
                    if (lane == 0) scal[1] = zz;
                }
                __syncthreads();
                const float invZ = 1.0f / scal[1];
                p0 = e0 * invZ; p1 = e1 * invZ; p2 = e2 * invZ; p3 = e3 * invZ;
            }

            // s = sum_n probs_n * p_n  (deterministic tree)
            float ps[OUTDIM];
#pragma unroll
            for (int j = 0; j < 16; j++) {
                float2 a = __half22float2(A[j]);
                float2 b2 = __half22float2(B[j]);
                float2 cc = __half22float2(spC[j]);
                float2 dd = __half22float2(spD[j]);
                ps[2 * j]     = p0 * a.x + p1 * b2.x + p2 * cc.x + p3 * dd.x;
                ps[2 * j + 1] = p0 * a.y + p1 * b2.y + p2 * cc.y + p3 * dd.y;
            }
#pragma unroll
            for (int s = 16; s; s >>= 1) {
#pragma unroll
                for (int o = 0; o < OUTDIM; o++)
                    ps[o] += __shfl_xor_sync(0xffffffffu, ps[o], s);
            }
            if (lane == 0) {
#pragma unroll
                for (int o = 0; o < OUTDIM; o++) wvec[wid * 32 + o] = ps[o];
            }
            __syncthreads();
            if (t < 32) {
                float sv = 0.f;
#pragma unroll
                for (int w = 0; w < NWARPS; w++) sv += wvec[w * 32 + t];
                sred[t] = sv;
            }
            __syncthreads();

            if (t < 32) {
                float nr = 0.f;
#pragma unroll
                for (int o = 0; o < OUTDIM; o++) { float sv = sred[o]; nr += sv * sv; }
                float scale = (nr / (1.0f + nr)) * rsqrtf(nr);
                float v = scale * sred[t];
                Vsh[t] += v;
                if (it == NITERS - 1)
                    out[((size_t)bout * NCAPS + c) * OUTDIM + t] = v;
            }
            __syncthreads();
        }
    }
}

extern "C" void kernel_launch(void* const* d_in, const int* in_sizes, int n_in,
                              void* d_out, int out_size)
{
    const float* x = (const float*)d_in[0];         // [64, 2048, 16]
    const float* W = (const float*)d_in[1];         // [32, 2048, 16, 32]
    float* out = (float*)d_out;                     // [64, 32, 32]

    cudaFuncSetAttribute(caps_route_kernel,
                         cudaFuncAttributeMaxDynamicSharedMemorySize, SMEM_BYTES);

    dim3 grid(NCAPS * (BATCH / 2));   // bid = c*32 + bp ; each CTA does batches 2bp, 2bp+1
    caps_route_kernel<<<grid, THREADS, SMEM_BYTES>>>(x, W, out);
}